// round 1
// baseline (speedup 1.0000x reference)
#include <cuda_runtime.h>
#include <cstdint>

#define D_FEAT 64
#define KNN    5
#define MAXN   10240
#define SPLITS 8
#define BM     64
#define BN     64
#define TPB    256
#define AST    68   // smem row stride (floats): 68*4=272 bytes, 16B-aligned rows

#define NEG_INF (-3.402823466e38f)

// Scratch (static device globals — no allocation allowed)
__device__ float g_sq[MAXN];
__device__ float g_topv[MAXN * SPLITS * KNN];
__device__ int   g_topi[MAXN * SPLITS * KNN];

__device__ __forceinline__ bool knn_better(float v, int i, float v2, int i2) {
    // larger value wins; on exact tie, lower index wins (jax top_k semantics)
    return (v > v2) || (v == v2 && i < i2);
}

// Insert into ascending-sorted top-K list (tv[0] = current k-th best).
// Fully unrolled, static indexing only -> stays in registers.
__device__ __forceinline__ void topk_insert5(float* tv, int* ti, float v, int i) {
    if (!knn_better(v, i, tv[0], ti[0])) return;
    bool cont = true;
#pragma unroll
    for (int s = 0; s < KNN; ++s) {
        bool up = (s < KNN - 1) && knn_better(v, i, tv[s + 1], ti[s + 1]);
        if (cont) {
            if (up) { tv[s] = tv[s + 1]; ti[s] = ti[s + 1]; }
            else    { tv[s] = v;          ti[s] = i; cont = false; }
        }
    }
}

// -------------------- squared norms --------------------
__global__ void sq_kernel(const float* __restrict__ x, int N) {
    int i = blockIdx.x * blockDim.x + threadIdx.x;
    if (i < N) {
        const float* xi = x + (size_t)i * D_FEAT;
        float s = 0.f;
#pragma unroll
        for (int k = 0; k < D_FEAT; ++k) s += xi[k] * xi[k];  // same FMA chain order as GEMM
        g_sq[i] = s;
    }
}

// -------------------- fused distance GEMM + per-split top-5 --------------------
// Block (rt, sp): rows [rt*64, rt*64+64) x column tiles {sp, sp+SPLITS, ...}
__global__ __launch_bounds__(TPB, 2)
void knn_topk_kernel(const float* __restrict__ x, int N) {
    // Pool sized for max(GEMM phase: 2*64*68 + 64 + 64 = 8832,
    //                    merge phase: 64*16*5*2        = 10240) floats
    __shared__ __align__(16) float pool[10240];
    float* As  = pool;                      // [D_FEAT][AST] transposed A tile
    float* Bs  = pool + D_FEAT * AST;       // [D_FEAT][AST] transposed B tile
    float* sqA = pool + 2 * D_FEAT * AST;   // [BM]
    float* sqB = sqA + BM;                  // [BN]

    const int rt   = blockIdx.x;
    const int sp   = blockIdx.y;
    const int row0 = rt * BM;
    const int tid  = threadIdx.x;
    const int tx   = tid & 15;   // 16 col-groups of 4
    const int ty   = tid >> 4;   // 16 row-groups of 4

    // Load A tile once (transposed): As[kk][r] = x[row0+r][kk]
    for (int idx = tid; idx < BM * D_FEAT; idx += TPB) {
        int r  = idx >> 6;
        int kk = idx & 63;
        int gr = row0 + r;
        As[kk * AST + r] = (gr < N) ? x[(size_t)gr * D_FEAT + kk] : 0.f;
    }
    if (tid < BM) {
        int gr = row0 + tid;
        sqA[tid] = (gr < N) ? g_sq[gr] : 0.f;
    }

    // Per-thread top-5 for the 4 rows it owns
    float tv[4][KNN];
    int   ti[4][KNN];
#pragma unroll
    for (int a = 0; a < 4; ++a)
#pragma unroll
        for (int m = 0; m < KNN; ++m) { tv[a][m] = NEG_INF; ti[a][m] = 0x7fffffff; }

    const int CT = (N + BN - 1) / BN;
    for (int ct = sp; ct < CT; ct += SPLITS) {
        const int col0 = ct * BN;
        __syncthreads();  // previous tile fully consumed (also covers As load on iter 0)
        for (int idx = tid; idx < BN * D_FEAT; idx += TPB) {
            int c  = idx >> 6;
            int kk = idx & 63;
            int gc = col0 + c;
            Bs[kk * AST + c] = (gc < N) ? x[(size_t)gc * D_FEAT + kk] : 0.f;
        }
        if (tid < BN) {
            int gc = col0 + tid;
            sqB[tid] = (gc < N) ? g_sq[gc] : 0.f;
        }
        __syncthreads();

        float acc[4][4];
#pragma unroll
        for (int a = 0; a < 4; ++a) { acc[a][0] = 0.f; acc[a][1] = 0.f; acc[a][2] = 0.f; acc[a][3] = 0.f; }

#pragma unroll
        for (int kk = 0; kk < D_FEAT; ++kk) {
            const float4 av = *reinterpret_cast<const float4*>(As + kk * AST + ty * 4);
            const float4 bv = *reinterpret_cast<const float4*>(Bs + kk * AST + tx * 4);
            acc[0][0] += av.x * bv.x; acc[0][1] += av.x * bv.y; acc[0][2] += av.x * bv.z; acc[0][3] += av.x * bv.w;
            acc[1][0] += av.y * bv.x; acc[1][1] += av.y * bv.y; acc[1][2] += av.y * bv.z; acc[1][3] += av.y * bv.w;
            acc[2][0] += av.z * bv.x; acc[2][1] += av.z * bv.y; acc[2][2] += av.z * bv.z; acc[2][3] += av.z * bv.w;
            acc[3][0] += av.w * bv.x; acc[3][1] += av.w * bv.y; acc[3][2] += av.w * bv.z; acc[3][3] += av.w * bv.w;
        }

        // D = (2*dot - xx_i) - xx_j  (exact association order of the reference)
#pragma unroll
        for (int a = 0; a < 4; ++a) {
            const float sa = sqA[ty * 4 + a];
#pragma unroll
            for (int b = 0; b < 4; ++b) {
                const int gc = col0 + tx * 4 + b;
                const float d = (2.f * acc[a][b] - sa) - sqB[tx * 4 + b];
                if (gc < N) topk_insert5(tv[a], ti[a], d, gc);
            }
        }
    }

    // -------- in-block merge: 16 threads per row -> one top-5 per (row, split) --------
    __syncthreads();  // done with As/Bs/sq — safe to reuse pool
    float* candV = pool;                                     // [BM][16][KNN]
    int*   candI = reinterpret_cast<int*>(pool + BM * 16 * KNN);
#pragma unroll
    for (int a = 0; a < 4; ++a) {
        const int r = ty * 4 + a;
#pragma unroll
        for (int m = 0; m < KNN; ++m) {
            candV[(r * 16 + tx) * KNN + m] = tv[a][m];
            candI[(r * 16 + tx) * KNN + m] = ti[a][m];
        }
    }
    __syncthreads();
    if (tid < BM) {
        const int gr = row0 + tid;
        if (gr < N) {
            float mv[KNN]; int mi[KNN];
#pragma unroll
            for (int m = 0; m < KNN; ++m) { mv[m] = NEG_INF; mi[m] = 0x7fffffff; }
            for (int t = 0; t < 16; ++t) {
#pragma unroll
                for (int m = 0; m < KNN; ++m) {
                    float v = candV[(tid * 16 + t) * KNN + m];
                    int   j = candI[(tid * 16 + t) * KNN + m];
                    if (j < N) topk_insert5(mv, mi, v, j);
                }
            }
#pragma unroll
            for (int m = 0; m < KNN; ++m) {
                g_topv[((size_t)gr * SPLITS + sp) * KNN + m] = mv[m];
                g_topi[((size_t)gr * SPLITS + sp) * KNN + m] = mi[m];
            }
        }
    }
}

// -------------------- final merge across splits + symmetric scatter --------------------
__global__ void merge_scatter_kernel(float* __restrict__ out, int N) {
    int i = blockIdx.x * blockDim.x + threadIdx.x;
    if (i >= N) return;
    float mv[KNN]; int mi[KNN];
#pragma unroll
    for (int m = 0; m < KNN; ++m) { mv[m] = NEG_INF; mi[m] = 0x7fffffff; }
    for (int s = 0; s < SPLITS; ++s) {
#pragma unroll
        for (int m = 0; m < KNN; ++m) {
            float v = g_topv[((size_t)i * SPLITS + s) * KNN + m];
            int   j = g_topi[((size_t)i * SPLITS + s) * KNN + m];
            if (j < N) topk_insert5(mv, mi, v, j);
        }
    }
    // top-5 always contains self (D[i][i]=0 is the row max); it lands on the
    // zeroed diagonal in the reference, so skip j == i here.
#pragma unroll
    for (int m = 0; m < KNN; ++m) {
        int j = mi[m]; float v = mv[m];
        if (j < N && j != i) {
            atomicAdd(out + (size_t)i * N + j, v);  // edges
            atomicAdd(out + (size_t)j * N + i, v);  // edges.T
        }
    }
}

extern "C" void kernel_launch(void* const* d_in, const int* in_sizes, int n_in,
                              void* d_out, int out_size) {
    const float* x = (const float*)d_in[0];
    // d_in[1] is k; this instance is fixed at k=5 (compile-time KNN).
    const int N = in_sizes[0] / D_FEAT;
    float* out = (float*)d_out;

    // Output is poisoned; zero it (part of the captured graph, replayed each run).
    cudaMemsetAsync(d_out, 0, (size_t)out_size * sizeof(float), 0);

    sq_kernel<<<(N + 255) / 256, 256>>>(x, N);

    dim3 grid((N + BM - 1) / BM, SPLITS);
    knn_topk_kernel<<<grid, TPB>>>(x, N);

    merge_scatter_kernel<<<(N + 255) / 256, 256>>>(out, N);
}

// round 4
// speedup vs baseline: 1.7415x; 1.7415x over previous
#include <cuda_runtime.h>
#include <cuda_fp16.h>
#include <cstdint>

// ======================= constants =======================
#define D_FEAT  64
#define KNN     5
#define KH      192        // 3 x 64 fp16 (hi/lo cross-term expansion)
#define BM      128
#define BN      64
#define TPB     256
#define SPLITS  16
#define NPADR   10112      // 79 * 128
#define NEG_INF (-3.402823466e38f)

// smem layout (bytes): row stride 400 (200 halfs) -> ldmatrix conflict-free
#define SAB     400
#define SM_A    0          // 128 x 400 = 51200
#define SM_B0   51200      // 64 x 400
#define SM_B1   76800      // 64 x 400
#define SM_SQB  102400     // 2 x 64 floats
#define SMEM_DYN 102912
// merge overlay (after GEMM loop, reuses B region):
#define SM_MV   51200                  // 128*8*5 floats = 20480 B
#define SM_MI   (51200 + 20480)       // 128*8*5 ints

// ======================= device scratch (static; no allocs) =======================
__device__ __half g_xa[(size_t)NPADR * KH];   // [hi, lo, hi]
__device__ __half g_xb[(size_t)NPADR * KH];   // [hi, hi, lo]
__device__ float  g_sq[NPADR];
__device__ float  g_topv[(size_t)NPADR * SPLITS * KNN];
__device__ int    g_topi[(size_t)NPADR * SPLITS * KNN];

// ======================= baseline-ISA PTX helpers (NO tcgen05) =======================
__device__ __forceinline__ uint32_t smem_to_u32(const void* p) {
    uint32_t a;
    asm("{ .reg .u64 t; cvta.to.shared.u64 t, %1; cvt.u32.u64 %0, t; }" : "=r"(a) : "l"(p));
    return a;
}
__device__ __forceinline__ void cp16(uint32_t dst, const void* src) {
    asm volatile("cp.async.cg.shared.global [%0], [%1], 16;" :: "r"(dst), "l"(src));
}
#define CP_COMMIT() asm volatile("cp.async.commit_group;" ::: "memory")
#define CP_WAIT(n)  asm volatile("cp.async.wait_group %0;" :: "n"(n) : "memory")

__device__ __forceinline__ void ldsm_x4(uint32_t* r, uint32_t addr) {
    asm volatile("ldmatrix.sync.aligned.m8n8.x4.shared.b16 {%0,%1,%2,%3}, [%4];"
                 : "=r"(r[0]), "=r"(r[1]), "=r"(r[2]), "=r"(r[3]) : "r"(addr));
}
__device__ __forceinline__ void mma16816(float* c, const uint32_t* a, const uint32_t* b) {
    asm volatile("mma.sync.aligned.m16n8k16.row.col.f32.f16.f16.f32 "
                 "{%0,%1,%2,%3}, {%4,%5,%6,%7}, {%8,%9}, {%0,%1,%2,%3};"
                 : "+f"(c[0]), "+f"(c[1]), "+f"(c[2]), "+f"(c[3])
                 : "r"(a[0]), "r"(a[1]), "r"(a[2]), "r"(a[3]), "r"(b[0]), "r"(b[1]));
}

// ======================= top-k =======================
__device__ __forceinline__ bool knn_better(float v, int i, float v2, int i2) {
    return (v > v2) || (v == v2 && i < i2);
}
__device__ __forceinline__ void topk_insert5(float* tv, int* ti, float v, int i) {
    bool cont = true;
#pragma unroll
    for (int s = 0; s < KNN; ++s) {
        bool up = (s < KNN - 1) && knn_better(v, i, tv[s + 1], ti[s + 1]);
        if (cont) {
            if (up) { tv[s] = tv[s + 1]; ti[s] = ti[s + 1]; }
            else    { tv[s] = v;          ti[s] = i; cont = false; }
        }
    }
}

// ======================= prep: fp16 hi/lo split + squared norms =======================
__global__ void prep_kernel(const float* __restrict__ x, int N) {
    int i = blockIdx.x * blockDim.x + threadIdx.x;
    if (i >= NPADR) return;
    __half* a = g_xa + (size_t)i * KH;
    __half* b = g_xb + (size_t)i * KH;
    const float* xr = x + (size_t)i * D_FEAT;
    float s = 0.f;
#pragma unroll 8
    for (int k = 0; k < D_FEAT; ++k) {
        float v = (i < N) ? xr[k] : 0.f;
        s += v * v;
        __half h = __float2half_rn(v);
        __half l = __float2half_rn(v - __half2float(h));
        a[k] = h; a[64 + k] = l; a[128 + k] = h;   // [hi, lo, hi]
        b[k] = h; b[64 + k] = h; b[128 + k] = l;   // [hi, hi, lo]
    }
    g_sq[i] = s;
}

// ======================= fused GEMM(k=192, mma.sync) + top-5 + zeroing =======================
__global__ __launch_bounds__(TPB, 2)
void gemm_knn_kernel(float* __restrict__ out, int N) {
    extern __shared__ __align__(16) char smem[];
    const uint32_t sb = smem_to_u32(smem);
    float* sqb = (float*)(smem + SM_SQB);   // [2][64]

    const int tid  = threadIdx.x;
    const int w    = tid >> 5;
    const int lane = tid & 31;
    const int wm   = w & 3;       // 4 M-warps
    const int wn   = w >> 2;      // 2 N-warps
    const int g    = lane >> 2;
    const int q    = lane & 3;
    const int rt   = blockIdx.x;
    const int sp   = blockIdx.y;
    const int row0 = rt * BM;

    const int NCT = (N + BN - 1) / BN;
    const int nt  = (NCT > sp) ? (NCT - sp + SPLITS - 1) / SPLITS : 0;

    // ---- per-thread ldmatrix base offsets (bytes within smem pool) ----
    const uint32_t aAddr0 = sb + SM_A + (uint32_t)(wm * 32 + (lane & 15)) * SAB + ((lane >> 4) * 8) * 2;
    const uint32_t aAddr1 = aAddr0 + 16 * SAB;
    const uint32_t bOff0  = (uint32_t)(wn * 32 + ((lane >> 4) << 3) + (lane & 7)) * SAB + (((lane >> 3) & 1) * 8) * 2;
    const uint32_t bOff1  = bOff0 + 16 * SAB;

    // ---- A tile -> smem via cp.async (128 rows x 24 x 16B) ----
    for (int idx = tid; idx < 128 * 24; idx += TPB) {
        int r = idx / 24, c = idx - r * 24;
        cp16(sb + SM_A + (uint32_t)r * SAB + c * 16,
             (const char*)(g_xa + (size_t)(row0 + r) * KH) + c * 16);
    }
    // ---- B(first tile) + sq ----
    {
        int ct0 = sp;
        for (int idx = tid; idx < 64 * 24; idx += TPB) {
            int r = idx / 24, c = idx - r * 24;
            cp16(sb + SM_B0 + (uint32_t)r * SAB + c * 16,
                 (const char*)(g_xb + (size_t)(ct0 * BN + r) * KH) + c * 16);
        }
        if (tid < BN) sqb[tid] = g_sq[ct0 * BN + tid];
    }
    CP_COMMIT();

    // ---- per-thread row constants + top-5 lists (4 rows/thread) ----
    float sa[4]; float tv[4][KNN]; int ti[4][KNN];
#pragma unroll
    for (int mb = 0; mb < 2; ++mb)
#pragma unroll
        for (int rr = 0; rr < 2; ++rr) {
            int li = mb * 2 + rr;
            sa[li] = g_sq[row0 + wm * 32 + mb * 16 + g + rr * 8];
#pragma unroll
            for (int m = 0; m < KNN; ++m) { tv[li][m] = NEG_INF; ti[li][m] = 0x7fffffff; }
        }

    // ---- zeroing assignment (this CTA's slice of the output, spread over tiles) ----
    const size_t Z    = (size_t)N * (size_t)N;
    const size_t GRID = (size_t)gridDim.x * SPLITS;
    const size_t per  = (((Z + GRID - 1) / GRID) + 3) & ~(size_t)3;
    const size_t zlo0 = ((size_t)sp * gridDim.x + rt) * per;
    const size_t zhiC = (zlo0 + per < Z) ? zlo0 + per : Z;
    const size_t zpi  = (nt > 0) ? ((((zhiC > zlo0 ? zhiC - zlo0 : 0) + nt - 1) / nt) + 3) & ~(size_t)3 : 0;

    for (int i = 0; i < nt; ++i) {
        const int ct  = sp + i * SPLITS;
        const int buf = i & 1;
        __syncthreads();   // all warps done reading the buffer we are about to overwrite
        if (i + 1 < nt) {
            const int ctn = sp + (i + 1) * SPLITS;
            const uint32_t bdst = sb + ((i + 1) & 1 ? SM_B1 : SM_B0);
            for (int idx = tid; idx < 64 * 24; idx += TPB) {
                int r = idx / 24, c = idx - r * 24;
                cp16(bdst + (uint32_t)r * SAB + c * 16,
                     (const char*)(g_xb + (size_t)(ctn * BN + r) * KH) + c * 16);
            }
            if (tid < BN) sqb[((i + 1) & 1) * BN + tid] = g_sq[ctn * BN + tid];
            CP_COMMIT();
            CP_WAIT(1);
        } else {
            CP_WAIT(0);
        }
        __syncthreads();

        // zero a slice of the output (overlaps with tensor work below)
        if (zpi) {
            size_t lo = zlo0 + (size_t)i * zpi;
            size_t hi = lo + zpi; if (hi > zhiC) hi = zhiC;
            for (size_t idx = lo + (size_t)tid * 4; idx + 4 <= hi; idx += (size_t)TPB * 4)
                __stcs((float4*)(out + idx), make_float4(0.f, 0.f, 0.f, 0.f));
            size_t tail = hi > lo ? (hi & ~(size_t)3) : lo;
            if (tail >= lo && (size_t)tid < (hi - tail)) __stcs(out + tail + tid, 0.f);
        }

        // ---- 128x64x192 tile: 12 k-steps, warp tile 32x32 ----
        float c[2][4][4];
#pragma unroll
        for (int mb = 0; mb < 2; ++mb)
#pragma unroll
            for (int nb = 0; nb < 4; ++nb)
#pragma unroll
                for (int e = 0; e < 4; ++e) c[mb][nb][e] = 0.f;

        const uint32_t bb = sb + (buf ? SM_B1 : SM_B0);
#pragma unroll
        for (int ks = 0; ks < 12; ++ks) {
            uint32_t a0[4], a1[4], b0[4], b1[4];
            ldsm_x4(a0, aAddr0 + ks * 32);
            ldsm_x4(a1, aAddr1 + ks * 32);
            ldsm_x4(b0, bb + bOff0 + ks * 32);   // regs 0,1 = n8-block0 ; 2,3 = block1
            ldsm_x4(b1, bb + bOff1 + ks * 32);   // blocks 2,3
            mma16816(c[0][0], a0, &b0[0]); mma16816(c[0][1], a0, &b0[2]);
            mma16816(c[0][2], a0, &b1[0]); mma16816(c[0][3], a0, &b1[2]);
            mma16816(c[1][0], a1, &b0[0]); mma16816(c[1][1], a1, &b0[2]);
            mma16816(c[1][2], a1, &b1[0]); mma16816(c[1][3], a1, &b1[2]);
        }

        // ---- epilogue: distances + top-5 (rare-insert guarded) ----
        const int colbase = ct * BN + wn * 32 + q * 2;
        float sqv[8];
#pragma unroll
        for (int nb = 0; nb < 4; ++nb) {
            sqv[nb * 2]     = sqb[buf * BN + wn * 32 + nb * 8 + q * 2];
            sqv[nb * 2 + 1] = sqb[buf * BN + wn * 32 + nb * 8 + q * 2 + 1];
        }
#pragma unroll
        for (int mb = 0; mb < 2; ++mb)
#pragma unroll
            for (int rr = 0; rr < 2; ++rr) {
                const int li = mb * 2 + rr;
                const float sal = sa[li];
#pragma unroll
                for (int nb = 0; nb < 4; ++nb)
#pragma unroll
                    for (int e0 = 0; e0 < 2; ++e0) {
                        const float dot = c[mb][nb][rr * 2 + e0];
                        const int   gc  = colbase + nb * 8 + e0;
                        const float d   = (2.f * dot - sal) - sqv[nb * 2 + e0];
                        if (gc < N && knn_better(d, gc, tv[li][0], ti[li][0]))
                            topk_insert5(tv[li], ti[li], d, gc);
                    }
            }
    }

    // ---- in-CTA merge: 8 contributor lists per row -> per-(row,split) top-5 ----
    __syncthreads();
    float* mvs = (float*)(smem + SM_MV);
    int*   mis = (int*)(smem + SM_MI);
#pragma unroll
    for (int mb = 0; mb < 2; ++mb)
#pragma unroll
        for (int rr = 0; rr < 2; ++rr) {
            const int li   = mb * 2 + rr;
            const int rloc = wm * 32 + mb * 16 + g + rr * 8;
            const int slot = wn * 4 + q;
            const int base = (rloc * 8 + slot) * KNN;
#pragma unroll
            for (int m = 0; m < KNN; ++m) { mvs[base + m] = tv[li][m]; mis[base + m] = ti[li][m]; }
        }
    __syncthreads();
    if (tid < BM) {
        float mv[KNN]; int mi[KNN];
#pragma unroll
        for (int m = 0; m < KNN; ++m) { mv[m] = NEG_INF; mi[m] = 0x7fffffff; }
        for (int s = 0; s < 8; ++s) {
#pragma unroll
            for (int m = 0; m < KNN; ++m) {
                float v = mvs[(tid * 8 + s) * KNN + m];
                int   j = mis[(tid * 8 + s) * KNN + m];
                if (j < N && knn_better(v, j, mv[0], mi[0])) topk_insert5(mv, mi, v, j);
            }
        }
        const int row = row0 + tid;
#pragma unroll
        for (int m = 0; m < KNN; ++m) {
            g_topv[((size_t)row * SPLITS + sp) * KNN + m] = mv[m];
            g_topi[((size_t)row * SPLITS + sp) * KNN + m] = mi[m];
        }
    }
}

// ======================= final merge across splits + symmetric scatter =======================
__global__ void merge_scatter_kernel(float* __restrict__ out, int N) {
    int i = blockIdx.x * blockDim.x + threadIdx.x;
    if (i >= N) return;
    float mv[KNN]; int mi[KNN];
#pragma unroll
    for (int m = 0; m < KNN; ++m) { mv[m] = NEG_INF; mi[m] = 0x7fffffff; }
    for (int s = 0; s < SPLITS; ++s) {
#pragma unroll
        for (int m = 0; m < KNN; ++m) {
            float v = g_topv[((size_t)i * SPLITS + s) * KNN + m];
            int   j = g_topi[((size_t)i * SPLITS + s) * KNN + m];
            if (j < N && knn_better(v, j, mv[0], mi[0])) topk_insert5(mv, mi, v, j);
        }
    }
    // self (D[i][i]~0) is always the row max -> occupies one slot; reference zeroes
    // the diagonal, so skip j == i. Off-diagonal: edges + edges.T via 2 atomics.
#pragma unroll
    for (int m = 0; m < KNN; ++m) {
        const int j = mi[m]; const float v = mv[m];
        if (j < N && j != i) {
            atomicAdd(out + (size_t)i * N + j, v);
            atomicAdd(out + (size_t)j * N + i, v);
        }
    }
}

// ======================= launch =======================
extern "C" void kernel_launch(void* const* d_in, const int* in_sizes, int n_in,
                              void* d_out, int out_size) {
    const float* x = (const float*)d_in[0];
    const int N = in_sizes[0] / D_FEAT;   // 10000 here (<= NPADR)
    float* out = (float*)d_out;

    cudaFuncSetAttribute(gemm_knn_kernel, cudaFuncAttributeMaxDynamicSharedMemorySize, SMEM_DYN);

    prep_kernel<<<(NPADR + 255) / 256, 256>>>(x, N);

    dim3 grid((N + BM - 1) / BM, SPLITS);
    gemm_knn_kernel<<<grid, TPB, SMEM_DYN>>>(out, N);

    merge_scatter_kernel<<<(N + 255) / 256, 256>>>(out, N);
}

// round 5
// speedup vs baseline: 2.1127x; 1.2131x over previous
#include <cuda_runtime.h>
#include <cuda_fp16.h>
#include <cstdint>

// ======================= constants =======================
#define D_FEAT  64
#define KNN     5
#define KH      192        // 3 x 64 fp16 (hi/lo cross-term expansion)
#define BM      128
#define BN      64
#define TPB     256
#define SPLITS  32
#define NPADR   10112      // 79 * 128
#define NEG_INF (-3.402823466e38f)

// smem layout (bytes): row stride 400 (200 halfs) -> ldmatrix conflict-free
#define SAB     400
#define SM_A    0          // 128 x 400 = 51200
#define SM_B0   51200      // 64 x 400
#define SM_B1   76800      // 64 x 400
#define SM_SQB  102400     // 2 x 64 floats
#define SMEM_DYN 102912
// merge overlay (after GEMM loop, reuses B region):
#define SM_MV   51200                  // 128*8*5 floats = 20480 B
#define SM_MI   (51200 + 20480)        // 128*8*5 ints

// ======================= device scratch (static; no allocs) =======================
__device__ __half g_xa[(size_t)NPADR * KH];   // [hi, lo, hi]
__device__ __half g_xb[(size_t)NPADR * KH];   // [hi, hi, lo]
__device__ float  g_sq[NPADR];
__device__ float  g_topv[(size_t)NPADR * SPLITS * KNN];
__device__ int    g_topi[(size_t)NPADR * SPLITS * KNN];

// ======================= baseline-ISA PTX helpers (NO tcgen05) =======================
__device__ __forceinline__ uint32_t smem_to_u32(const void* p) {
    uint32_t a;
    asm("{ .reg .u64 t; cvta.to.shared.u64 t, %1; cvt.u32.u64 %0, t; }" : "=r"(a) : "l"(p));
    return a;
}
__device__ __forceinline__ void cp16(uint32_t dst, const void* src) {
    asm volatile("cp.async.cg.shared.global [%0], [%1], 16;" :: "r"(dst), "l"(src));
}
#define CP_COMMIT() asm volatile("cp.async.commit_group;" ::: "memory")
#define CP_WAIT(n)  asm volatile("cp.async.wait_group %0;" :: "n"(n) : "memory")

__device__ __forceinline__ void ldsm_x4(uint32_t* r, uint32_t addr) {
    asm volatile("ldmatrix.sync.aligned.m8n8.x4.shared.b16 {%0,%1,%2,%3}, [%4];"
                 : "=r"(r[0]), "=r"(r[1]), "=r"(r[2]), "=r"(r[3]) : "r"(addr));
}
__device__ __forceinline__ void mma16816(float* c, const uint32_t* a, const uint32_t* b) {
    asm volatile("mma.sync.aligned.m16n8k16.row.col.f32.f16.f16.f32 "
                 "{%0,%1,%2,%3}, {%4,%5,%6,%7}, {%8,%9}, {%0,%1,%2,%3};"
                 : "+f"(c[0]), "+f"(c[1]), "+f"(c[2]), "+f"(c[3])
                 : "r"(a[0]), "r"(a[1]), "r"(a[2]), "r"(a[3]), "r"(b[0]), "r"(b[1]));
}

// ======================= top-k =======================
__device__ __forceinline__ bool knn_better(float v, int i, float v2, int i2) {
    return (v > v2) || (v == v2 && i < i2);
}
__device__ __forceinline__ void topk_insert5(float* tv, int* ti, float v, int i) {
    bool cont = true;
#pragma unroll
    for (int s = 0; s < KNN; ++s) {
        bool up = (s < KNN - 1) && knn_better(v, i, tv[s + 1], ti[s + 1]);
        if (cont) {
            if (up) { tv[s] = tv[s + 1]; ti[s] = ti[s + 1]; }
            else    { tv[s] = v;          ti[s] = i; cont = false; }
        }
    }
}

// ======================= prep: element-parallel fp16 split + warp-reduced norms ======
// One thread per (row, 4-feature chunk): 16 threads per row, NPADR*16 threads total.
__global__ void prep_kernel(const float* __restrict__ x, int N) {
    const int idx = blockIdx.x * blockDim.x + threadIdx.x;
    if (idx >= NPADR * 16) return;
    const int i  = idx >> 4;        // row
    const int kq = idx & 15;        // 4-feature chunk
    const int k  = kq * 4;

    float4 v4 = make_float4(0.f, 0.f, 0.f, 0.f);
    if (i < N) v4 = *(const float4*)(x + (size_t)i * D_FEAT + k);

    // hi/lo split of 4 values
    __half h[4], l[4];
    const float vv[4] = {v4.x, v4.y, v4.z, v4.w};
    float psum = 0.f;
#pragma unroll
    for (int e = 0; e < 4; ++e) {
        psum += vv[e] * vv[e];
        h[e] = __float2half_rn(vv[e]);
        l[e] = __float2half_rn(vv[e] - __half2float(h[e]));
    }
    // pack 4 halves into 8 bytes
    uint2 hp, lp;
    hp.x = __half_as_ushort(h[0]) | ((uint32_t)__half_as_ushort(h[1]) << 16);
    hp.y = __half_as_ushort(h[2]) | ((uint32_t)__half_as_ushort(h[3]) << 16);
    lp.x = __half_as_ushort(l[0]) | ((uint32_t)__half_as_ushort(l[1]) << 16);
    lp.y = __half_as_ushort(l[2]) | ((uint32_t)__half_as_ushort(l[3]) << 16);

    __half* a = g_xa + (size_t)i * KH;
    __half* b = g_xb + (size_t)i * KH;
    *(uint2*)(a + k)        = hp;  // A: [hi, lo, hi]
    *(uint2*)(a + 64 + k)   = lp;
    *(uint2*)(a + 128 + k)  = hp;
    *(uint2*)(b + k)        = hp;  // B: [hi, hi, lo]
    *(uint2*)(b + 64 + k)   = hp;
    *(uint2*)(b + 128 + k)  = lp;

    // row-norm: reduce psum across the 16 lanes of this row (rows are lane-aligned:
    // 16 threads per row, 2 rows per warp)
#pragma unroll
    for (int s = 8; s > 0; s >>= 1) psum += __shfl_xor_sync(0xffffffffu, psum, s);
    if (kq == 0) g_sq[i] = psum;
}

// ======================= fused GEMM(k=192, mma.sync) + top-5 + zeroing =======================
__global__ __launch_bounds__(TPB, 2)
void gemm_knn_kernel(float* __restrict__ out, int N) {
    extern __shared__ __align__(16) char smem[];
    const uint32_t sb = smem_to_u32(smem);
    float* sqb = (float*)(smem + SM_SQB);   // [2][64]

    const int tid  = threadIdx.x;
    const int w    = tid >> 5;
    const int lane = tid & 31;
    const int wm   = w & 3;       // 4 M-warps
    const int wn   = w >> 2;      // 2 N-warps
    const int g    = lane >> 2;
    const int q    = lane & 3;
    const int rt   = blockIdx.x;
    const int sp   = blockIdx.y;
    const int row0 = rt * BM;

    const int NCT = (N + BN - 1) / BN;
    const int nt  = (NCT > sp) ? (NCT - sp + SPLITS - 1) / SPLITS : 0;

    // ---- per-thread ldmatrix base offsets (bytes within smem pool) ----
    const uint32_t aAddr0 = sb + SM_A + (uint32_t)(wm * 32 + (lane & 15)) * SAB + ((lane >> 4) * 8) * 2;
    const uint32_t aAddr1 = aAddr0 + 16 * SAB;
    const uint32_t bOff0  = (uint32_t)(wn * 32 + ((lane >> 4) << 3) + (lane & 7)) * SAB + (((lane >> 3) & 1) * 8) * 2;
    const uint32_t bOff1  = bOff0 + 16 * SAB;

    // ---- A tile -> smem via cp.async (128 rows x 24 x 16B) ----
    for (int idx = tid; idx < 128 * 24; idx += TPB) {
        int r = idx / 24, c = idx - r * 24;
        cp16(sb + SM_A + (uint32_t)r * SAB + c * 16,
             (const char*)(g_xa + (size_t)(row0 + r) * KH) + c * 16);
    }
    // ---- B(first tile) + sq ----
    if (nt > 0) {
        int ct0 = sp;
        for (int idx = tid; idx < 64 * 24; idx += TPB) {
            int r = idx / 24, c = idx - r * 24;
            cp16(sb + SM_B0 + (uint32_t)r * SAB + c * 16,
                 (const char*)(g_xb + (size_t)(ct0 * BN + r) * KH) + c * 16);
        }
        if (tid < BN) sqb[tid] = g_sq[ct0 * BN + tid];
    }
    CP_COMMIT();

    // ---- per-thread row constants + top-5 lists (4 rows/thread) ----
    float sa[4]; float tv[4][KNN]; int ti[4][KNN];
#pragma unroll
    for (int mb = 0; mb < 2; ++mb)
#pragma unroll
        for (int rr = 0; rr < 2; ++rr) {
            int li = mb * 2 + rr;
            sa[li] = g_sq[row0 + wm * 32 + mb * 16 + g + rr * 8];
#pragma unroll
            for (int m = 0; m < KNN; ++m) { tv[li][m] = NEG_INF; ti[li][m] = 0x7fffffff; }
        }

    // ---- zeroing assignment (this CTA's slice of the output, spread over tiles) ----
    const size_t Z    = (size_t)N * (size_t)N;
    const size_t GRID = (size_t)gridDim.x * SPLITS;
    const size_t per  = (((Z + GRID - 1) / GRID) + 3) & ~(size_t)3;
    const size_t zlo0 = ((size_t)sp * gridDim.x + rt) * per;
    const size_t zhiC = (zlo0 + per < Z) ? zlo0 + per : Z;
    const size_t zpi  = (nt > 0) ? ((((zhiC > zlo0 ? zhiC - zlo0 : 0) + nt - 1) / nt) + 3) & ~(size_t)3 : 0;

    for (int i = 0; i < nt; ++i) {
        const int ct  = sp + i * SPLITS;
        const int buf = i & 1;
        __syncthreads();   // all warps done reading the buffer we are about to overwrite
        if (i + 1 < nt) {
            const int ctn = sp + (i + 1) * SPLITS;
            const uint32_t bdst = sb + ((i + 1) & 1 ? SM_B1 : SM_B0);
            for (int idx = tid; idx < 64 * 24; idx += TPB) {
                int r = idx / 24, c = idx - r * 24;
                cp16(bdst + (uint32_t)r * SAB + c * 16,
                     (const char*)(g_xb + (size_t)(ctn * BN + r) * KH) + c * 16);
            }
            if (tid < BN) sqb[((i + 1) & 1) * BN + tid] = g_sq[ctn * BN + tid];
            CP_COMMIT();
            CP_WAIT(1);
        } else {
            CP_WAIT(0);
        }
        __syncthreads();

        // zero a slice of the output (overlaps with tensor work below)
        if (zpi) {
            size_t lo = zlo0 + (size_t)i * zpi;
            size_t hi = lo + zpi; if (hi > zhiC) hi = zhiC;
            if (hi > lo) {
                for (size_t idx = lo + (size_t)tid * 4; idx + 4 <= hi; idx += (size_t)TPB * 4)
                    __stcs((float4*)(out + idx), make_float4(0.f, 0.f, 0.f, 0.f));
                size_t tail = hi & ~(size_t)3;
                if (tail >= lo && (size_t)tid < (hi - tail)) __stcs(out + tail + tid, 0.f);
            }
        }

        // ---- 128x64x192 tile: 12 k-steps, warp tile 32x32 ----
        float c[2][4][4];
#pragma unroll
        for (int mb = 0; mb < 2; ++mb)
#pragma unroll
            for (int nb = 0; nb < 4; ++nb)
#pragma unroll
                for (int e = 0; e < 4; ++e) c[mb][nb][e] = 0.f;

        const uint32_t bb = sb + (buf ? SM_B1 : SM_B0);
#pragma unroll
        for (int ks = 0; ks < 12; ++ks) {
            uint32_t a0[4], a1[4], b0[4], b1[4];
            ldsm_x4(a0, aAddr0 + ks * 32);
            ldsm_x4(a1, aAddr1 + ks * 32);
            ldsm_x4(b0, bb + bOff0 + ks * 32);   // regs 0,1 = n8-block0 ; 2,3 = block1
            ldsm_x4(b1, bb + bOff1 + ks * 32);   // blocks 2,3
            mma16816(c[0][0], a0, &b0[0]); mma16816(c[0][1], a0, &b0[2]);
            mma16816(c[0][2], a0, &b1[0]); mma16816(c[0][3], a0, &b1[2]);
            mma16816(c[1][0], a1, &b0[0]); mma16816(c[1][1], a1, &b0[2]);
            mma16816(c[1][2], a1, &b1[0]); mma16816(c[1][3], a1, &b1[2]);
        }

        // ---- epilogue: distances + top-5 (rare-insert guarded) ----
        const int colbase = ct * BN + wn * 32 + q * 2;
        float sqv[8];
#pragma unroll
        for (int nb = 0; nb < 4; ++nb) {
            sqv[nb * 2]     = sqb[buf * BN + wn * 32 + nb * 8 + q * 2];
            sqv[nb * 2 + 1] = sqb[buf * BN + wn * 32 + nb * 8 + q * 2 + 1];
        }
#pragma unroll
        for (int mb = 0; mb < 2; ++mb)
#pragma unroll
            for (int rr = 0; rr < 2; ++rr) {
                const int li = mb * 2 + rr;
                const float sal = sa[li];
#pragma unroll
                for (int nb = 0; nb < 4; ++nb)
#pragma unroll
                    for (int e0 = 0; e0 < 2; ++e0) {
                        const float dot = c[mb][nb][rr * 2 + e0];
                        const int   gc  = colbase + nb * 8 + e0;
                        const float d   = (2.f * dot - sal) - sqv[nb * 2 + e0];
                        if (gc < N && knn_better(d, gc, tv[li][0], ti[li][0]))
                            topk_insert5(tv[li], ti[li], d, gc);
                    }
            }
    }

    // ---- in-CTA merge: 8 contributor lists per row -> per-(row,split) top-5 ----
    __syncthreads();
    float* mvs = (float*)(smem + SM_MV);
    int*   mis = (int*)(smem + SM_MI);
#pragma unroll
    for (int mb = 0; mb < 2; ++mb)
#pragma unroll
        for (int rr = 0; rr < 2; ++rr) {
            const int li   = mb * 2 + rr;
            const int rloc = wm * 32 + mb * 16 + g + rr * 8;
            const int slot = wn * 4 + q;
            const int base = (rloc * 8 + slot) * KNN;
#pragma unroll
            for (int m = 0; m < KNN; ++m) { mvs[base + m] = tv[li][m]; mis[base + m] = ti[li][m]; }
        }
    __syncthreads();
    if (tid < BM) {
        float mv[KNN]; int mi[KNN];
#pragma unroll
        for (int m = 0; m < KNN; ++m) { mv[m] = NEG_INF; mi[m] = 0x7fffffff; }
        for (int s = 0; s < 8; ++s) {
#pragma unroll
            for (int m = 0; m < KNN; ++m) {
                float v = mvs[(tid * 8 + s) * KNN + m];
                int   j = mis[(tid * 8 + s) * KNN + m];
                if (j < N && knn_better(v, j, mv[0], mi[0])) topk_insert5(mv, mi, v, j);
            }
        }
        const int row = row0 + tid;
#pragma unroll
        for (int m = 0; m < KNN; ++m) {
            g_topv[((size_t)row * SPLITS + sp) * KNN + m] = mv[m];
            g_topi[((size_t)row * SPLITS + sp) * KNN + m] = mi[m];
        }
    }
}

// ======================= final merge across splits + symmetric scatter =======================
__global__ void merge_scatter_kernel(float* __restrict__ out, int N) {
    int i = blockIdx.x * blockDim.x + threadIdx.x;
    if (i >= N) return;
    float mv[KNN]; int mi[KNN];
#pragma unroll
    for (int m = 0; m < KNN; ++m) { mv[m] = NEG_INF; mi[m] = 0x7fffffff; }
    for (int s = 0; s < SPLITS; ++s) {
#pragma unroll
        for (int m = 0; m < KNN; ++m) {
            float v = g_topv[((size_t)i * SPLITS + s) * KNN + m];
            int   j = g_topi[((size_t)i * SPLITS + s) * KNN + m];
            if (j < N && knn_better(v, j, mv[0], mi[0])) topk_insert5(mv, mi, v, j);
        }
    }
    // self (D[i][i]~0) is always the row max -> occupies one slot; reference zeroes
    // the diagonal, so skip j == i. Off-diagonal: edges + edges.T via 2 atomics.
#pragma unroll
    for (int m = 0; m < KNN; ++m) {
        const int j = mi[m]; const float v = mv[m];
        if (j < N && j != i) {
            atomicAdd(out + (size_t)i * N + j, v);
            atomicAdd(out + (size_t)j * N + i, v);
        }
    }
}

// ======================= launch =======================
extern "C" void kernel_launch(void* const* d_in, const int* in_sizes, int n_in,
                              void* d_out, int out_size) {
    const float* x = (const float*)d_in[0];
    const int N = in_sizes[0] / D_FEAT;   // 10000 here (<= NPADR)
    float* out = (float*)d_out;

    cudaFuncSetAttribute(gemm_knn_kernel, cudaFuncAttributeMaxDynamicSharedMemorySize, SMEM_DYN);

    prep_kernel<<<(NPADR * 16 + 255) / 256, 256>>>(x, N);

    dim3 grid((N + BM - 1) / BM, SPLITS);
    gemm_knn_kernel<<<grid, TPB, SMEM_DYN>>>(out, N);

    merge_scatter_kernel<<<(N + 255) / 256, 256>>>(out, N);
}